// round 4
// baseline (speedup 1.0000x reference)
#include <cuda_runtime.h>
#include <cuda_bf16.h>
#include <mma.h>

using namespace nvcuda;

#define INPN 1024
#define NN   8000
#define NEE  6400
#define NII  1600
#define TS   1000
#define TSP  1024   /* padded t rows for GEMM */
#define T0   16     /* transient steps on the grid */
#define PRB0 200
#define NWE  200    /* NEE/32 */
#define NWI  50     /* NII/32 */
#define DECAYF 0.95f
#define VTHF   0.5f

#define SIM_NB 25
#define SIM_NT 320
#define WPC    10

#define ST_NT  512  /* steady kernel threads */
#define NPT    16   /* neurons per thread (512*16 = 8192 slots, 8000 used) */

// ---------------- device scratch (static: no allocation APIs) ----------------
__device__ float         d_Dp[(size_t)TSP * NN];
__device__ __nv_bfloat16 d_S[(size_t)TSP * INPN];
__device__ __nv_bfloat16 d_Whi[(size_t)INPN * NN];
__device__ __nv_bfloat16 d_Wlo[(size_t)INPN * NN];
__device__ float    d_csEae[NEE];
__device__ float    d_csIae[NEE];
__device__ float    d_csEai[NII];
__device__ float    d_csIai[NII];
__device__ unsigned d_mE[3][NWE];
__device__ unsigned d_mI[3][NWI];
__device__ int      d_cE[T0];
__device__ int      d_cI[T0];
__device__ float    d_v[NN];
__device__ volatile unsigned d_barcnt;

// ---------------- K0: reset ----------------
__global__ void k_reset() {
  int tid = blockIdx.x * blockDim.x + threadIdx.x;
  int total = T0 * 2 + NEE * 2 + NII * 2;
  for (int i = tid; i < total; i += gridDim.x * blockDim.x) {
    int x = i;
    if (x < T0) { d_cE[x] = 0; continue; } x -= T0;
    if (x < T0) { d_cI[x] = 0; continue; } x -= T0;
    if (x < NEE) { d_csEae[x] = 0.f; continue; } x -= NEE;
    if (x < NEE) { d_csIae[x] = 0.f; continue; } x -= NEE;
    if (x < NII) { d_csEai[x] = 0.f; continue; } x -= NII;
    d_csIai[x] = 0.f;
  }
  if (tid == 0) d_barcnt = 0u;
}

// ---------------- K1: spike matrix S (bf16 0/1, padded) ----------------
__global__ void k_spk(const float* __restrict__ inp, const float* __restrict__ rand_p) {
  int idx = blockIdx.x * blockDim.x + threadIdx.x;
  if (idx >= TSP * INPN) return;
  int t = idx >> 10, i = idx & 1023;
  float v = 0.f;
  if (t < TS) v = (rand_p[(size_t)t * INPN + i] <= inp[i] * 0.5f) ? 1.f : 0.f;
  d_S[idx] = __float2bfloat16(v);
}

// ---------------- K2: hi/lo bf16 split of input-weight rows ----------------
__global__ void k_wsplit(const float* __restrict__ w_ae, const float* __restrict__ w_ai) {
  int idx = blockIdx.x * blockDim.x + threadIdx.x;
  if (idx >= INPN * NN) return;
  int k = idx / NN, j = idx - k * NN;
  float w = (j < NEE) ? w_ae[(size_t)k * NEE + j] : w_ai[(size_t)k * NII + (j - NEE)];
  __nv_bfloat16 hi = __float2bfloat16(w);
  float lo = w - __bfloat162float(hi);
  d_Whi[idx] = hi;
  d_Wlo[idx] = __float2bfloat16(lo);
}

// ---------------- K3: column sums ----------------
__global__ void k_colsum(const float* __restrict__ W, int ncols, int which) {
  int j = blockIdx.x * blockDim.x + threadIdx.x;
  if (j >= ncols) return;
  int c = blockIdx.y;
  int base = (c < 32) ? (INPN + c * 200) : (INPN + NEE + (c - 32) * 200);
  const float* p = W + (size_t)base * ncols + j;
  float s = 0.f;
#pragma unroll 8
  for (int r = 0; r < 200; ++r) s += p[(size_t)r * ncols];
  float* dst;
  if (c < 32) dst = which ? d_csEai : d_csEae;
  else        dst = which ? d_csIai : d_csIae;
  atomicAdd(&dst[j], s);
}

// ---------------- K4: tensor-core GEMM D = S x (Whi + Wlo) ----------------
__global__ void __launch_bounds__(128) k_gemm() {
  __shared__ __nv_bfloat16 sA [64][72];
  __shared__ __nv_bfloat16 sBh[64][72];
  __shared__ __nv_bfloat16 sBl[64][72];

  const int bn = blockIdx.x, bm = blockIdx.y;
  const int tid = threadIdx.x;
  const int warp = tid >> 5;
  const int wm = warp >> 1, wn = warp & 1;

  wmma::fragment<wmma::accumulator, 16, 16, 16, float> acc[2][2];
#pragma unroll
  for (int mm = 0; mm < 2; ++mm)
#pragma unroll
    for (int nn = 0; nn < 2; ++nn) wmma::fill_fragment(acc[mm][nn], 0.0f);

  for (int kt = 0; kt < 16; ++kt) {
#pragma unroll
    for (int u = 0; u < 4; ++u) {
      int idx = tid + u * 128;
      int row = idx >> 3, c8 = idx & 7;
      *(uint4*)&sA[row][c8 * 8] =
          *(const uint4*)&d_S[(size_t)(bm * 64 + row) * INPN + kt * 64 + c8 * 8];
    }
#pragma unroll
    for (int u = 0; u < 4; ++u) {
      int idx = tid + u * 128;
      int row = idx >> 3, c8 = idx & 7;
      size_t g = (size_t)(kt * 64 + row) * NN + bn * 64 + c8 * 8;
      *(uint4*)&sBh[row][c8 * 8] = *(const uint4*)&d_Whi[g];
      *(uint4*)&sBl[row][c8 * 8] = *(const uint4*)&d_Wlo[g];
    }
    __syncthreads();

#pragma unroll
    for (int kk = 0; kk < 4; ++kk) {
      wmma::fragment<wmma::matrix_a, 16, 16, 16, __nv_bfloat16, wmma::row_major> af[2];
      wmma::fragment<wmma::matrix_b, 16, 16, 16, __nv_bfloat16, wmma::row_major> bh[2], bl[2];
#pragma unroll
      for (int mm = 0; mm < 2; ++mm)
        wmma::load_matrix_sync(af[mm], &sA[wm * 32 + mm * 16][kk * 16], 72);
#pragma unroll
      for (int nn = 0; nn < 2; ++nn) {
        wmma::load_matrix_sync(bh[nn], &sBh[kk * 16][wn * 32 + nn * 16], 72);
        wmma::load_matrix_sync(bl[nn], &sBl[kk * 16][wn * 32 + nn * 16], 72);
      }
#pragma unroll
      for (int mm = 0; mm < 2; ++mm)
#pragma unroll
        for (int nn = 0; nn < 2; ++nn) {
          wmma::mma_sync(acc[mm][nn], af[mm], bh[nn], acc[mm][nn]);
          wmma::mma_sync(acc[mm][nn], af[mm], bl[nn], acc[mm][nn]);
        }
    }
    __syncthreads();
  }

#pragma unroll
  for (int mm = 0; mm < 2; ++mm)
#pragma unroll
    for (int nn = 0; nn < 2; ++nn) {
      int r0 = bm * 64 + wm * 32 + mm * 16;
      int c0 = bn * 64 + wn * 32 + nn * 16;
      wmma::store_matrix_sync(&d_Dp[(size_t)r0 * NN + c0], acc[mm][nn], NN,
                              wmma::mem_row_major);
    }
}

// ---------------- K5: transient (grid-barrier) t = 0..T0-1 ----------------
__device__ __forceinline__ float gather_group(const float* __restrict__ base, int stride,
                                              const unsigned* __restrict__ mask,
                                              int cnt, int gsize, int nw, float colsum) {
  if (cnt == 0)     return 0.f;
  if (cnt == gsize) return colsum;
  bool comp = (2 * cnt > gsize);
  float acc = comp ? colsum : 0.f;
  float sgn = comp ? -1.f : 1.f;
  for (int wd = 0; wd < nw; ++wd) {
    unsigned x = __ldcg(&mask[wd]);
    if (comp) x = ~x;
    while (x) {
      int b = __ffs(x) - 1;
      x &= x - 1;
      acc = fmaf(sgn, __ldg(base + (size_t)(wd * 32 + b) * stride), acc);
    }
  }
  return acc;
}

__global__ void __launch_bounds__(SIM_NT, 1) k_trans(const float* __restrict__ w_ae,
                                                     const float* __restrict__ w_ai) {
  __shared__ int s_pc[WPC];
  const int tid = blockIdx.x * SIM_NT + threadIdx.x;   // 0..7999
  const bool isE = (tid < NEE);
  const int col = isE ? tid : tid - NEE;
  const int stride = isE ? NEE : NII;
  const float* W = isE ? w_ae : w_ai;
  const float* baseE = W + (size_t)INPN * stride + col;
  const float* baseI = W + (size_t)(INPN + NEE) * stride + col;
  const float csE = isE ? d_csEae[col] : d_csEai[col];
  const float csI = isE ? d_csIae[col] : d_csIai[col];
  float v = 0.f;
  const unsigned nb = gridDim.x;

  for (int t = 0; t < T0; ++t) {
    float a = __ldg(&d_Dp[(size_t)t * NN + tid]);
    int ageE = t - (isE ? 2 : 1);
    int ageI = t - (isE ? 1 : 2);
    if (ageE >= 0) {
      int c = __ldcg(&d_cE[ageE]);
      a += gather_group(baseE, stride, d_mE[ageE % 3], c, NEE, NWE, csE);
    }
    if (ageI >= 0) {
      int c = __ldcg(&d_cI[ageI]);
      a += gather_group(baseI, stride, d_mI[ageI % 3], c, NII, NWI, csI);
    }
    v = v * DECAYF + a;
    bool sp = (v >= VTHF);
    if (sp) v = 0.f;

    unsigned bal = __ballot_sync(0xffffffffu, sp);
    if ((threadIdx.x & 31) == 0) {
      int gw = tid >> 5;
      int s = t % 3;
      if (isE) d_mE[s][gw] = bal;
      else     d_mI[s][gw - NWE] = bal;
      s_pc[threadIdx.x >> 5] = __popc(bal);
    }
    __syncthreads();
    if (threadIdx.x == 0) {
      int tot = 0;
#pragma unroll
      for (int w = 0; w < WPC; ++w) tot += s_pc[w];
      if (isE) atomicAdd(&d_cE[t], tot);
      else     atomicAdd(&d_cI[t], tot);
      __threadfence();
      atomicAdd((unsigned*)&d_barcnt, 1u);
      unsigned want = (unsigned)(t + 1) * nb;
      while (d_barcnt < want) { }
      __threadfence();
    }
    __syncthreads();
  }
  d_v[tid] = v;
}

// ---------------- K6: steady state, ONE CTA, smem masks, BAR.RED flags ----------------
// rare path: gather from smem masks (mask words identical across threads)
__device__ __noinline__ float gather_sm(const unsigned* __restrict__ mw, int nw,
                                        const float* __restrict__ base, int stride,
                                        float colsum) {
  int cnt = 0;
  for (int w = 0; w < nw; ++w) cnt += __popc(mw[w]);
  if (cnt == 0) return 0.f;
  if (cnt == nw * 32) return colsum;
  bool comp = (2 * cnt > nw * 32);
  float acc = comp ? colsum : 0.f;
  float sgn = comp ? -1.f : 1.f;
  for (int w = 0; w < nw; ++w) {
    unsigned x = mw[w];
    if (comp) x = ~x;
    while (x) {
      int b = __ffs(x) - 1;
      x &= x - 1;
      acc = fmaf(sgn, __ldg(base + (size_t)(32 * w + b) * stride), acc);
    }
  }
  return acc;
}

__global__ void __launch_bounds__(ST_NT, 1) k_steady(const float* __restrict__ w_ae,
                                                     const float* __restrict__ w_ai,
                                                     float* __restrict__ out) {
  __shared__ unsigned s_m[3][256];   // words 0..199 E, 200..249 I
  const int tid = threadIdx.x, warp = tid >> 5, lane = tid & 31;

  float v[NPT], cse[NPT], csi[NPT], ssum[NPT];
  bool isE[NPT], alive[NPT];
#pragma unroll
  for (int r = 0; r < NPT; ++r) {
    int j = tid + ST_NT * r;
    alive[r] = (j < NN);
    isE[r] = (j < NEE);
    ssum[r] = 0.f;
    if (alive[r]) {
      v[r] = d_v[j];
      if (isE[r]) { cse[r] = d_csEae[j];       csi[r] = d_csIae[j]; }
      else        { cse[r] = d_csEai[j - NEE]; csi[r] = d_csIae == 0 ? 0.f : d_csIai[j - NEE]; }
    } else { v[r] = 0.f; cse[r] = 0.f; csi[r] = 0.f; }
  }
  // preload masks of steps T0-1, T0-2 into their t%3 slots
  for (int w = tid; w < 250 * 2; w += ST_NT) {
    int s = w < 250 ? (T0 - 1) % 3 : (T0 - 2) % 3;
    int ww = w % 250;
    s_m[s][ww] = (ww < NWE) ? d_mE[s][ww] : d_mI[s][ww - NWE];
  }
  int fE1 = (d_cE[T0 - 1] == NEE), fE2 = (d_cE[T0 - 2] == NEE);
  int fI1 = (d_cI[T0 - 1] == NII), fI2 = (d_cI[T0 - 2] == NII);
  __syncthreads();

  for (int t = T0; t < TS; ++t) {
    const int sl1 = (t - 1) % 3, sl2 = (t - 2) % 3, slw = t % 3;
    int predE = 1, predI = 1;
    bool sp[NPT];
#pragma unroll
    for (int r = 0; r < NPT; ++r) {
      if (!alive[r]) { sp[r] = false; continue; }
      int j = tid + ST_NT * r;
      float a = __ldg(&d_Dp[(size_t)t * NN + j]);
      if (isE[r]) {
        // E target: E rows @ t-2, I rows @ t-1
        if (fE2) a += cse[r];
        else a += gather_sm(&s_m[sl2][0], NWE, w_ae + (size_t)INPN * NEE + j, NEE, cse[r]);
        if (fI1) a += csi[r];
        else a += gather_sm(&s_m[sl1][NWE], NWI, w_ae + (size_t)(INPN + NEE) * NEE + j, NEE, csi[r]);
      } else {
        int c = j - NEE;
        if (fE1) a += cse[r];
        else a += gather_sm(&s_m[sl1][0], NWE, w_ai + (size_t)INPN * NII + c, NII, cse[r]);
        if (fI2) a += csi[r];
        else a += gather_sm(&s_m[sl2][NWE], NWI, w_ai + (size_t)(INPN + NEE) * NII + c, NII, csi[r]);
      }
      float nv = v[r] * DECAYF + a;
      bool s_ = (nv >= VTHF);
      v[r] = s_ ? 0.f : nv;
      sp[r] = s_;
      if (s_ && isE[r] && t >= PRB0) ssum[r] += 1.f;
      if (alive[r]) {
        if (isE[r]) predE &= (int)s_;
        else        predI &= (int)s_;
      }
    }
    // publish masks: word = 16*r + warp, bit = lane
#pragma unroll
    for (int r = 0; r < NPT; ++r) {
      unsigned bal = __ballot_sync(0xffffffffu, sp[r]);
      int w = 16 * r + warp;
      if (lane == 0 && w < 250) s_m[slw][w] = bal;
    }
    int nfE = __syncthreads_and(predE);
    int nfI = __syncthreads_and(predI);
    fE2 = fE1; fE1 = nfE;
    fI2 = fI1; fI1 = nfI;
  }
#pragma unroll
  for (int r = 0; r < NPT; ++r) {
    int j = tid + ST_NT * r;
    if (alive[r] && isE[r]) out[j] = ssum[r] * (1.0f / 800.0f);
  }
}

// ---------------- launcher ----------------
extern "C" void kernel_launch(void* const* d_in, const int* in_sizes, int n_in,
                              void* d_out, int out_size) {
  const float *inp = 0, *w_ae = 0, *w_ai = 0, *rand_p = 0;
  for (int i = 0; i < n_in; ++i) {
    switch (in_sizes[i]) {
      case 1024:      inp    = (const float*)d_in[i]; break;
      case 57753600:  w_ae   = (const float*)d_in[i]; break;
      case 14438400:  w_ai   = (const float*)d_in[i]; break;
      case 1024000:   rand_p = (const float*)d_in[i]; break;
    }
  }
  float* out = (float*)d_out;

  k_reset<<<32, 256>>>();
  k_spk<<<(TSP * INPN + 255) / 256, 256>>>(inp, rand_p);
  k_wsplit<<<(INPN * NN + 255) / 256, 256>>>(w_ae, w_ai);
  {
    dim3 g((NEE + 255) / 256, 40);
    k_colsum<<<g, 256>>>(w_ae, NEE, 0);
  }
  {
    dim3 g((NII + 255) / 256, 40);
    k_colsum<<<g, 256>>>(w_ai, NII, 1);
  }
  {
    dim3 g(NN / 64, TSP / 64);
    k_gemm<<<g, 128>>>();
  }
  k_trans<<<SIM_NB, SIM_NT>>>(w_ae, w_ai);
  k_steady<<<1, ST_NT>>>(w_ae, w_ai, out);
}

// round 5
// speedup vs baseline: 3.1767x; 3.1767x over previous
#include <cuda_runtime.h>
#include <cuda_bf16.h>
#include <mma.h>
#include <cstdint>

using namespace nvcuda;

#define INPN 1024
#define NN   8000
#define NEE  6400
#define NII  1600
#define TS   1000
#define TSP  1024   /* padded t rows for GEMM */
#define T0   12     /* transient steps simulated exactly */
#define PRB0 200
#define NWE  200    /* NEE/32 */
#define NWI  50     /* NII/32 */
#define DECAYF 0.95f
#define VTHF   0.5f
#define EPSF   1e-3f

#define SIM_NB 25
#define SIM_NT 320
#define WPC    10

// ---------------- device scratch (static: no allocation APIs) ----------------
__device__ float         d_Dp[(size_t)TSP * NN];
__device__ __nv_bfloat16 d_S[(size_t)TSP * INPN];
__device__ __nv_bfloat16 d_Whi[(size_t)INPN * NN];
__device__ __nv_bfloat16 d_Wlo[(size_t)INPN * NN];
__device__ float    d_csEae[NEE];
__device__ float    d_csIae[NEE];
__device__ float    d_csEai[NII];
__device__ float    d_csIai[NII];
__device__ unsigned d_mE[3][NWE];
__device__ unsigned d_mI[3][NWI];
__device__ int      d_cE[TS];
__device__ int      d_cI[TS];
__device__ float    d_v[NN];
__device__ int      d_fail;                 // earliest step where saturation breaks
__device__ volatile unsigned d_barcnt;      // barrier counter for k_trans
__device__ volatile unsigned d_barcnt2;     // barrier counter for k_fix

// ---------------- K0: reset ----------------
__global__ void k_reset() {
  int tid = blockIdx.x * blockDim.x + threadIdx.x;
  int total = TS * 2 + NEE * 2 + NII * 2;
  for (int i = tid; i < total; i += gridDim.x * blockDim.x) {
    int x = i;
    if (x < TS) { d_cE[x] = 0; continue; } x -= TS;
    if (x < TS) { d_cI[x] = 0; continue; } x -= TS;
    if (x < NEE) { d_csEae[x] = 0.f; continue; } x -= NEE;
    if (x < NEE) { d_csIae[x] = 0.f; continue; } x -= NEE;
    if (x < NII) { d_csEai[x] = 0.f; continue; } x -= NII;
    d_csIai[x] = 0.f;
  }
  if (tid == 0) { d_barcnt = 0u; d_barcnt2 = 0u; d_fail = 0x7fffffff; }
}

// ---------------- K1: spike matrix S (bf16 0/1, padded) ----------------
__global__ void k_spk(const float* __restrict__ inp, const float* __restrict__ rand_p) {
  int idx = blockIdx.x * blockDim.x + threadIdx.x;
  if (idx >= TSP * INPN) return;
  int t = idx >> 10, i = idx & 1023;
  float v = 0.f;
  if (t < TS) v = (rand_p[(size_t)t * INPN + i] <= inp[i] * 0.5f) ? 1.f : 0.f;
  d_S[idx] = __float2bfloat16(v);
}

// ---------------- K2: hi/lo bf16 split of input-weight rows ----------------
__global__ void k_wsplit(const float* __restrict__ w_ae, const float* __restrict__ w_ai) {
  int idx = blockIdx.x * blockDim.x + threadIdx.x;
  if (idx >= INPN * NN) return;
  int k = idx / NN, j = idx - k * NN;
  float w = (j < NEE) ? w_ae[(size_t)k * NEE + j] : w_ai[(size_t)k * NII + (j - NEE)];
  __nv_bfloat16 hi = __float2bfloat16(w);
  float lo = w - __bfloat162float(hi);
  d_Whi[idx] = hi;
  d_Wlo[idx] = __float2bfloat16(lo);
}

// ---------------- K3: column sums of E-row / I-row blocks ----------------
__global__ void k_colsum(const float* __restrict__ W, int ncols, int which) {
  int j = blockIdx.x * blockDim.x + threadIdx.x;
  if (j >= ncols) return;
  int c = blockIdx.y;
  int base = (c < 32) ? (INPN + c * 200) : (INPN + NEE + (c - 32) * 200);
  const float* p = W + (size_t)base * ncols + j;
  float s = 0.f;
#pragma unroll 8
  for (int r = 0; r < 200; ++r) s += p[(size_t)r * ncols];
  float* dst;
  if (c < 32) dst = which ? d_csEai : d_csEae;
  else        dst = which ? d_csIai : d_csIae;
  atomicAdd(&dst[j], s);
}

// ---------------- K4: tensor-core GEMM D = S x (Whi+Wlo) + saturation-check epilogue ----------------
__global__ void __launch_bounds__(128) k_gemm() {
  __shared__ __nv_bfloat16 sA [64][72];
  __shared__ __nv_bfloat16 sBh[64][72];
  __shared__ __nv_bfloat16 sBl[64][72];

  const int bn = blockIdx.x, bm = blockIdx.y;
  const int tid = threadIdx.x;
  const int warp = tid >> 5;
  const int wm = warp >> 1, wn = warp & 1;

  wmma::fragment<wmma::accumulator, 16, 16, 16, float> acc[2][2];
#pragma unroll
  for (int mm = 0; mm < 2; ++mm)
#pragma unroll
    for (int nn = 0; nn < 2; ++nn) wmma::fill_fragment(acc[mm][nn], 0.0f);

  for (int kt = 0; kt < 16; ++kt) {
#pragma unroll
    for (int u = 0; u < 4; ++u) {
      int idx = tid + u * 128;
      int row = idx >> 3, c8 = idx & 7;
      *(uint4*)&sA[row][c8 * 8] =
          *(const uint4*)&d_S[(size_t)(bm * 64 + row) * INPN + kt * 64 + c8 * 8];
    }
#pragma unroll
    for (int u = 0; u < 4; ++u) {
      int idx = tid + u * 128;
      int row = idx >> 3, c8 = idx & 7;
      size_t g = (size_t)(kt * 64 + row) * NN + bn * 64 + c8 * 8;
      *(uint4*)&sBh[row][c8 * 8] = *(const uint4*)&d_Whi[g];
      *(uint4*)&sBl[row][c8 * 8] = *(const uint4*)&d_Wlo[g];
    }
    __syncthreads();

#pragma unroll
    for (int kk = 0; kk < 4; ++kk) {
      wmma::fragment<wmma::matrix_a, 16, 16, 16, __nv_bfloat16, wmma::row_major> af[2];
      wmma::fragment<wmma::matrix_b, 16, 16, 16, __nv_bfloat16, wmma::row_major> bh[2], bl[2];
#pragma unroll
      for (int mm = 0; mm < 2; ++mm)
        wmma::load_matrix_sync(af[mm], &sA[wm * 32 + mm * 16][kk * 16], 72);
#pragma unroll
      for (int nn = 0; nn < 2; ++nn) {
        wmma::load_matrix_sync(bh[nn], &sBh[kk * 16][wn * 32 + nn * 16], 72);
        wmma::load_matrix_sync(bl[nn], &sBl[kk * 16][wn * 32 + nn * 16], 72);
      }
#pragma unroll
      for (int mm = 0; mm < 2; ++mm)
#pragma unroll
        for (int nn = 0; nn < 2; ++nn) {
          wmma::mma_sync(acc[mm][nn], af[mm], bh[nn], acc[mm][nn]);
          wmma::mma_sync(acc[mm][nn], af[mm], bl[nn], acc[mm][nn]);
        }
    }
    __syncthreads();
  }

#pragma unroll
  for (int mm = 0; mm < 2; ++mm)
#pragma unroll
    for (int nn = 0; nn < 2; ++nn) {
      int r0 = bm * 64 + wm * 32 + mm * 16;
      int c0 = bn * 64 + wn * 32 + nn * 16;
      wmma::store_matrix_sync(&d_Dp[(size_t)r0 * NN + c0], acc[mm][nn], NN,
                              wmma::mem_row_major);
    }
  __syncthreads();   // make all warps' global tile stores visible to the whole CTA

  // --- saturation-check epilogue: spike at t iff D[t][j] + K_j >= VTH (v reset to 0) ---
  int minfail = 0x7fffffff;
  for (int idx = tid; idx < 64 * 64; idx += 128) {
    int r = idx >> 6, c = idx & 63;
    int t = bm * 64 + r;
    if (t >= T0 && t < TS) {
      int j = bn * 64 + c;
      float K = (j < NEE) ? (d_csEae[j] + d_csIae[j])
                          : (d_csEai[j - NEE] + d_csIai[j - NEE]);
      float dv = d_Dp[(size_t)t * NN + j];
      if (dv + K < VTHF + EPSF && t < minfail) minfail = t;
    }
  }
  if (minfail != 0x7fffffff) atomicMin(&d_fail, minfail);
}

// ---------------- gather helper (exact path) ----------------
__device__ __forceinline__ float gather_group(const float* __restrict__ base, int stride,
                                              const unsigned* __restrict__ mask,
                                              int cnt, int gsize, int nw, float colsum) {
  if (cnt == 0)     return 0.f;
  if (cnt == gsize) return colsum;
  bool comp = (2 * cnt > gsize);
  float acc = comp ? colsum : 0.f;
  float sgn = comp ? -1.f : 1.f;
  for (int wd = 0; wd < nw; ++wd) {
    unsigned x = __ldcg(&mask[wd]);
    if (comp) x = ~x;
    while (x) {
      int b = __ffs(x) - 1;
      x &= x - 1;
      acc = fmaf(sgn, __ldg(base + (size_t)(wd * 32 + b) * stride), acc);
    }
  }
  return acc;
}

// ---------------- K5: transient exact sim t = 0..T0-1 (grid barrier) ----------------
__global__ void __launch_bounds__(SIM_NT, 1) k_trans(const float* __restrict__ w_ae,
                                                     const float* __restrict__ w_ai) {
  __shared__ int s_pc[WPC];
  const int tid = blockIdx.x * SIM_NT + threadIdx.x;   // 0..7999
  const bool isE = (tid < NEE);
  const int col = isE ? tid : tid - NEE;
  const int stride = isE ? NEE : NII;
  const float* W = isE ? w_ae : w_ai;
  const float* baseE = W + (size_t)INPN * stride + col;
  const float* baseI = W + (size_t)(INPN + NEE) * stride + col;
  const float csE = isE ? d_csEae[col] : d_csEai[col];
  const float csI = isE ? d_csIae[col] : d_csIai[col];
  float v = 0.f;
  const unsigned nb = gridDim.x;

  for (int t = 0; t < T0; ++t) {
    float a = __ldg(&d_Dp[(size_t)t * NN + tid]);
    int ageE = t - (isE ? 2 : 1);
    int ageI = t - (isE ? 1 : 2);
    if (ageE >= 0) {
      int c = __ldcg(&d_cE[ageE]);
      a += gather_group(baseE, stride, d_mE[ageE % 3], c, NEE, NWE, csE);
    }
    if (ageI >= 0) {
      int c = __ldcg(&d_cI[ageI]);
      a += gather_group(baseI, stride, d_mI[ageI % 3], c, NII, NWI, csI);
    }
    v = v * DECAYF + a;
    bool sp = (v >= VTHF);
    if (sp) v = 0.f;

    unsigned bal = __ballot_sync(0xffffffffu, sp);
    if ((threadIdx.x & 31) == 0) {
      int gw = tid >> 5;
      int s = t % 3;
      if (isE) d_mE[s][gw] = bal;
      else     d_mI[s][gw - NWE] = bal;
      s_pc[threadIdx.x >> 5] = __popc(bal);
    }
    __syncthreads();
    if (threadIdx.x == 0) {
      int tot = 0;
#pragma unroll
      for (int w = 0; w < WPC; ++w) tot += s_pc[w];
      if (isE) atomicAdd(&d_cE[t], tot);
      else     atomicAdd(&d_cI[t], tot);
      __threadfence();
      atomicAdd((unsigned*)&d_barcnt, 1u);
      unsigned want = (unsigned)(t + 1) * nb;
      while (d_barcnt < want) { }
      __threadfence();
    }
    __syncthreads();
  }
  d_v[tid] = v;
}

// ---------------- K6: handoff check + optimistic output ----------------
__global__ void k_out(float* __restrict__ out) {
  int j = blockIdx.x * blockDim.x + threadIdx.x;
  if (j == 0) {
    if (d_cE[T0 - 1] != NEE || d_cI[T0 - 1] != NII ||
        d_cE[T0 - 2] != NEE || d_cI[T0 - 2] != NII)
      atomicMin(&d_fail, T0);
  }
  if (j < NEE) out[j] = 1.0f;   // saturated: 800 spikes / 800
}

// ---------------- K7: exact fallback sim t = T0..TS-1 (normally exits instantly) ----------------
__global__ void __launch_bounds__(SIM_NT, 1) k_fix(const float* __restrict__ w_ae,
                                                   const float* __restrict__ w_ai,
                                                   float* __restrict__ out) {
  if (*(volatile int*)&d_fail >= TS) return;   // saturation verified: nothing to do

  __shared__ int s_pc[WPC];
  const int tid = blockIdx.x * SIM_NT + threadIdx.x;
  const bool isE = (tid < NEE);
  const int col = isE ? tid : tid - NEE;
  const int stride = isE ? NEE : NII;
  const float* W = isE ? w_ae : w_ai;
  const float* baseE = W + (size_t)INPN * stride + col;
  const float* baseI = W + (size_t)(INPN + NEE) * stride + col;
  const float csE = isE ? d_csEae[col] : d_csEai[col];
  const float csI = isE ? d_csIae[col] : d_csIai[col];
  float v = d_v[tid];
  float ssum = 0.f;
  const unsigned nb = gridDim.x;

  for (int t = T0; t < TS; ++t) {
    float a = __ldg(&d_Dp[(size_t)t * NN + tid]);
    int ageE = t - (isE ? 2 : 1);
    int ageI = t - (isE ? 1 : 2);
    {
      int c = __ldcg(&d_cE[ageE]);
      a += gather_group(baseE, stride, d_mE[ageE % 3], c, NEE, NWE, csE);
    }
    {
      int c = __ldcg(&d_cI[ageI]);
      a += gather_group(baseI, stride, d_mI[ageI % 3], c, NII, NWI, csI);
    }
    v = v * DECAYF + a;
    bool sp = (v >= VTHF);
    if (sp) v = 0.f;
    if (sp && isE && t >= PRB0) ssum += 1.f;

    unsigned bal = __ballot_sync(0xffffffffu, sp);
    if ((threadIdx.x & 31) == 0) {
      int gw = tid >> 5;
      int s = t % 3;
      if (isE) d_mE[s][gw] = bal;
      else     d_mI[s][gw - NWE] = bal;
      s_pc[threadIdx.x >> 5] = __popc(bal);
    }
    __syncthreads();
    if (threadIdx.x == 0) {
      int tot = 0;
#pragma unroll
      for (int w = 0; w < WPC; ++w) tot += s_pc[w];
      if (isE) atomicAdd(&d_cE[t], tot);
      else     atomicAdd(&d_cI[t], tot);
      __threadfence();
      atomicAdd((unsigned*)&d_barcnt2, 1u);
      unsigned want = (unsigned)(t - T0 + 1) * nb;
      while (d_barcnt2 < want) { }
      __threadfence();
    }
    __syncthreads();
  }
  if (isE) out[col] = ssum * (1.0f / 800.0f);
}

// ---------------- launcher ----------------
extern "C" void kernel_launch(void* const* d_in, const int* in_sizes, int n_in,
                              void* d_out, int out_size) {
  const float *inp = 0, *w_ae = 0, *w_ai = 0, *rand_p = 0;
  for (int i = 0; i < n_in; ++i) {
    switch (in_sizes[i]) {
      case 1024:      inp    = (const float*)d_in[i]; break;
      case 57753600:  w_ae   = (const float*)d_in[i]; break;
      case 14438400:  w_ai   = (const float*)d_in[i]; break;
      case 1024000:   rand_p = (const float*)d_in[i]; break;
    }
  }
  float* out = (float*)d_out;

  k_reset<<<32, 256>>>();
  k_spk<<<(TSP * INPN + 255) / 256, 256>>>(inp, rand_p);
  k_wsplit<<<(INPN * NN + 255) / 256, 256>>>(w_ae, w_ai);
  {
    dim3 g((NEE + 255) / 256, 40);
    k_colsum<<<g, 256>>>(w_ae, NEE, 0);
  }
  {
    dim3 g((NII + 255) / 256, 40);
    k_colsum<<<g, 256>>>(w_ai, NII, 1);
  }
  {
    dim3 g(NN / 64, TSP / 64);
    k_gemm<<<g, 128>>>();
  }
  k_trans<<<SIM_NB, SIM_NT>>>(w_ae, w_ai);
  k_out<<<(NEE + 255) / 256, 256>>>(out);
  k_fix<<<SIM_NB, SIM_NT>>>(w_ae, w_ai, out);
}